// round 5
// baseline (speedup 1.0000x reference)
#include <cuda_runtime.h>

#define NUc 50000
#define NVc 50000
#define ESc 800000
#define ERc 1000000
#define AS 68   // smem A-tile stride (floats): 272B rows, 16B aligned, bank-skewed
#define WS 68   // smem W-tile stride

// ---------------- device scratch (no allocations allowed) ----------------
__device__ __align__(16) float g_s_social[(size_t)NUc * 64];
__device__ __align__(16) float g_s_ru[(size_t)NUc * 64];
__device__ __align__(16) float g_s_rv[(size_t)NVc * 64];
__device__ float g_deg_s[NUc];
__device__ float g_deg_ru[NUc];
__device__ float g_deg_rv[NVc];
__device__ __align__(16) float g_hu[(size_t)NUc * 64];
__device__ __align__(16) float g_hv[(size_t)NVc * 64];
__device__ __align__(16) float g_tu[(size_t)NUc * 64];
__device__ __align__(16) float g_tv[(size_t)NVc * 64];
__device__ __align__(16) float g_xu[(size_t)NUc * 64];
__device__ __align__(16) float g_xv[(size_t)NVc * 64];
__device__ __align__(16) float g_y1[(size_t)ERc * 64];   // 256 MB
__device__ __align__(16) float g_y2[(size_t)ERc * 16];   // 64 MB
__device__ double g_statU[128];
__device__ double g_statV[128];
__device__ double g_stat1[128];
__device__ double g_stat2[32];
__device__ __align__(16) float g_affU[128];
__device__ __align__(16) float g_affV[128];
__device__ __align__(16) float g_aff1[128];
__device__ __align__(16) float g_aff2[32];

// ---------------- zero scratch ----------------
__global__ void k_zero() {
    size_t tid = (size_t)blockIdx.x * blockDim.x + threadIdx.x;
    size_t stride = (size_t)gridDim.x * blockDim.x;
    const size_t n4 = (size_t)NUc * 16;  // float4 count of a [NU,64] array (NV==NU)
    float4 z = make_float4(0.f, 0.f, 0.f, 0.f);
    for (size_t j = tid; j < n4; j += stride) {
        ((float4*)g_s_social)[j] = z;
        ((float4*)g_s_ru)[j] = z;
        ((float4*)g_s_rv)[j] = z;
    }
    for (size_t j = tid; j < NUc; j += stride) {
        g_deg_s[j] = 0.f;
        g_deg_ru[j] = 0.f;
        g_deg_rv[j] = 0.f;
    }
    if (tid < 128) { g_statU[tid] = 0.0; g_statV[tid] = 0.0; g_stat1[tid] = 0.0; }
    if (tid < 32) g_stat2[tid] = 0.0;
}

// ---------------- edge scatter: acc[dst] += feat[src], deg[dst] += 1 ----------------
__global__ __launch_bounds__(256) void k_scatter(
    const float* __restrict__ feat, const int* __restrict__ src,
    const int* __restrict__ dst, float* __restrict__ acc,
    float* __restrict__ deg, int E) {
    int w = (int)((blockIdx.x * blockDim.x + threadIdx.x) >> 5);
    int lane = threadIdx.x & 31;
    if (w >= E) return;
    int s = __ldg(src + w);
    int d = __ldg(dst + w);
    float2 v = __ldg((const float2*)feat + (size_t)s * 32 + lane);
    float* base = acc + (size_t)d * 64 + lane * 2;
    atomicAdd(base + 0, v.x);
    atomicAdd(base + 1, v.y);
    if (lane == 0) atomicAdd(deg + d, 1.0f);
}

// ---------------- shared GEMM helpers (64-row block, 256 threads) ----------------
__device__ __forceinline__ void mma64(const float* __restrict__ As_,
                                      const float* __restrict__ Ws_,
                                      int ty, int tx, float acc[4][4]) {
#pragma unroll 16
    for (int k = 0; k < 64; k++) {
        float4 b = *(const float4*)(Ws_ + k * WS + tx * 4);
        float a0 = As_[(ty * 4 + 0) * AS + k];
        float a1 = As_[(ty * 4 + 1) * AS + k];
        float a2 = As_[(ty * 4 + 2) * AS + k];
        float a3 = As_[(ty * 4 + 3) * AS + k];
        acc[0][0] += a0 * b.x; acc[0][1] += a0 * b.y; acc[0][2] += a0 * b.z; acc[0][3] += a0 * b.w;
        acc[1][0] += a1 * b.x; acc[1][1] += a1 * b.y; acc[1][2] += a1 * b.z; acc[1][3] += a1 * b.w;
        acc[2][0] += a2 * b.x; acc[2][1] += a2 * b.y; acc[2][2] += a2 * b.z; acc[2][3] += a2 * b.w;
        acc[3][0] += a3 * b.x; acc[3][1] += a3 * b.y; acc[3][2] += a3 * b.z; acc[3][3] += a3 * b.w;
    }
}

__device__ __forceinline__ void loadW(const float* __restrict__ W, float* __restrict__ Ws_) {
    int t = threadIdx.x, r = t >> 2, cg = (t & 3) << 4;
#pragma unroll
    for (int j = 0; j < 16; j += 4) {
        float4 v = *(const float4*)(W + r * 64 + cg + j);
        *(float4*)(Ws_ + r * WS + cg + j) = v;
    }
}

__device__ __forceinline__ void loadWsum(const float* __restrict__ Wa, const float* __restrict__ Wb,
                                         float* __restrict__ Ws_) {
    int t = threadIdx.x, r = t >> 2, cg = (t & 3) << 4;
#pragma unroll
    for (int j = 0; j < 16; j += 4) {
        float4 a = *(const float4*)(Wa + r * 64 + cg + j);
        float4 b = *(const float4*)(Wb + r * 64 + cg + j);
        *(float4*)(Ws_ + r * WS + cg + j) = make_float4(a.x + b.x, a.y + b.y, a.z + b.z, a.w + b.w);
    }
}

__device__ __forceinline__ void loadA_plain(const float* __restrict__ src, int rowBase, int N,
                                            float* __restrict__ As_) {
    int t = threadIdx.x, r = t >> 2, cg = (t & 3) << 4;
    int row = rowBase + r;
#pragma unroll
    for (int j = 0; j < 16; j += 4) {
        float4 v = make_float4(0.f, 0.f, 0.f, 0.f);
        if (row < N) v = *(const float4*)(src + (size_t)row * 64 + cg + j);
        *(float4*)(As_ + r * AS + cg + j) = v;
    }
}

__device__ __forceinline__ void loadA_mean(const float* __restrict__ src, const float* __restrict__ deg,
                                           int rowBase, int N, float* __restrict__ As_) {
    int t = threadIdx.x, r = t >> 2, cg = (t & 3) << 4;
    int row = rowBase + r;
    float sc = 0.f;
    if (row < N) sc = 1.f / fmaxf(__ldg(deg + row), 1.f);
#pragma unroll
    for (int j = 0; j < 16; j += 4) {
        float4 v = make_float4(0.f, 0.f, 0.f, 0.f);
        if (row < N) {
            v = *(const float4*)(src + (size_t)row * 64 + cg + j);
            v.x *= sc; v.y *= sc; v.z *= sc; v.w *= sc;
        }
        *(float4*)(As_ + r * AS + cg + j) = v;
    }
}

__device__ __forceinline__ void loadA_bnrelu(const float* __restrict__ src, const float* __restrict__ aff,
                                             int rowBase, int N, float* __restrict__ As_) {
    int t = threadIdx.x, r = t >> 2, cg = (t & 3) << 4;
    int row = rowBase + r;
#pragma unroll
    for (int j = 0; j < 16; j += 4) {
        float4 v = make_float4(0.f, 0.f, 0.f, 0.f);
        if (row < N) {
            v = *(const float4*)(src + (size_t)row * 64 + cg + j);
            float4 a = *(const float4*)(aff + cg + j);
            float4 c = *(const float4*)(aff + 64 + cg + j);
            v.x = fmaxf(v.x * a.x + c.x, 0.f);
            v.y = fmaxf(v.y * a.y + c.y, 0.f);
            v.z = fmaxf(v.z * a.z + c.z, 0.f);
            v.w = fmaxf(v.w * a.w + c.w, 0.f);
        }
        *(float4*)(As_ + r * AS + cg + j) = v;
    }
}

// ---------------- node combine: h_u = u2e@(Ws0+Ws2) + (b0+b2) + meanS@Wn0 + meanRu@Wn2 ----------------
__global__ __launch_bounds__(256) void k_comb_user(
    const float* __restrict__ u2e, const float* __restrict__ Wself,
    const float* __restrict__ bself, const float* __restrict__ Wneigh,
    float* __restrict__ out) {
    __shared__ __align__(16) float As_[64 * AS];
    __shared__ __align__(16) float Ws_[64 * WS];
    int t = threadIdx.x, tx = t & 15, ty = t >> 4;
    int rowBase = blockIdx.x * 64;
    float acc[4][4] = {};

    loadA_plain(u2e, rowBase, NUc, As_);
    loadWsum(Wself, Wself + 2 * 4096, Ws_);
    __syncthreads();
    mma64(As_, Ws_, ty, tx, acc);
    __syncthreads();

    loadA_mean(g_s_social, g_deg_s, rowBase, NUc, As_);
    loadW(Wneigh, Ws_);
    __syncthreads();
    mma64(As_, Ws_, ty, tx, acc);
    __syncthreads();

    loadA_mean(g_s_ru, g_deg_ru, rowBase, NUc, As_);
    loadW(Wneigh + 2 * 4096, Ws_);
    __syncthreads();
    mma64(As_, Ws_, ty, tx, acc);

    float4 b0 = *(const float4*)(bself + tx * 4);
    float4 b2 = *(const float4*)(bself + 128 + tx * 4);
    float4 bias = make_float4(b0.x + b2.x, b0.y + b2.y, b0.z + b2.z, b0.w + b2.w);
#pragma unroll
    for (int i = 0; i < 4; i++) {
        int row = rowBase + ty * 4 + i;
        if (row < NUc) {
            *(float4*)(out + (size_t)row * 64 + tx * 4) =
                make_float4(acc[i][0] + bias.x, acc[i][1] + bias.y,
                            acc[i][2] + bias.z, acc[i][3] + bias.w);
        }
    }
}

// ---------------- node combine items: h_v = v2e@Ws1 + b1 + meanRv@Wn1 ----------------
__global__ __launch_bounds__(256) void k_comb_item(
    const float* __restrict__ v2e, const float* __restrict__ Wself,
    const float* __restrict__ bself, const float* __restrict__ Wneigh,
    float* __restrict__ out) {
    __shared__ __align__(16) float As_[64 * AS];
    __shared__ __align__(16) float Ws_[64 * WS];
    int t = threadIdx.x, tx = t & 15, ty = t >> 4;
    int rowBase = blockIdx.x * 64;
    float acc[4][4] = {};

    loadA_plain(v2e, rowBase, NVc, As_);
    loadW(Wself + 4096, Ws_);
    __syncthreads();
    mma64(As_, Ws_, ty, tx, acc);
    __syncthreads();

    loadA_mean(g_s_rv, g_deg_rv, rowBase, NVc, As_);
    loadW(Wneigh + 4096, Ws_);
    __syncthreads();
    mma64(As_, Ws_, ty, tx, acc);

    float4 bias = *(const float4*)(bself + 64 + tx * 4);
#pragma unroll
    for (int i = 0; i < 4; i++) {
        int row = rowBase + ty * 4 + i;
        if (row < NVc) {
            *(float4*)(out + (size_t)row * 64 + tx * 4) =
                make_float4(acc[i][0] + bias.x, acc[i][1] + bias.y,
                            acc[i][2] + bias.z, acc[i][3] + bias.w);
        }
    }
}

// ---------------- tower stage 1: out = in@W + b, accumulate column stats ----------------
__global__ __launch_bounds__(256) void k_tower1(
    const float* __restrict__ in, const float* __restrict__ W, const float* __restrict__ b,
    float* __restrict__ out, double* __restrict__ stats, int N) {
    __shared__ __align__(16) float As_[64 * AS];
    __shared__ __align__(16) float Ws_[64 * WS];
    __shared__ float ssum[64], ssq[64];
    int t = threadIdx.x, tx = t & 15, ty = t >> 4;
    if (t < 64) { ssum[t] = 0.f; ssq[t] = 0.f; }
    int rowBase = blockIdx.x * 64;

    loadA_plain(in, rowBase, N, As_);
    loadW(W, Ws_);
    __syncthreads();
    float acc[4][4] = {};
    mma64(As_, Ws_, ty, tx, acc);

    float4 bias = *(const float4*)(b + tx * 4);
    float cs[4] = {0, 0, 0, 0}, cq[4] = {0, 0, 0, 0};
#pragma unroll
    for (int i = 0; i < 4; i++) {
        int row = rowBase + ty * 4 + i;
        if (row < N) {
            float v0 = acc[i][0] + bias.x, v1 = acc[i][1] + bias.y;
            float v2 = acc[i][2] + bias.z, v3 = acc[i][3] + bias.w;
            *(float4*)(out + (size_t)row * 64 + tx * 4) = make_float4(v0, v1, v2, v3);
            cs[0] += v0; cq[0] += v0 * v0;
            cs[1] += v1; cq[1] += v1 * v1;
            cs[2] += v2; cq[2] += v2 * v2;
            cs[3] += v3; cq[3] += v3 * v3;
        }
    }
#pragma unroll
    for (int j = 0; j < 4; j++) {
        atomicAdd(&ssum[tx * 4 + j], cs[j]);
        atomicAdd(&ssq[tx * 4 + j], cq[j]);
    }
    __syncthreads();
    if (t < 64) atomicAdd(&stats[t], (double)ssum[t]);
    else if (t < 128) atomicAdd(&stats[t], (double)ssq[t - 64]);
}

// ---------------- BN finalize: aff = [gamma*rsqrt(var+eps)][beta - mean*a] ----------------
__global__ void k_fin(const double* __restrict__ stats, const float* __restrict__ gamma,
                      const float* __restrict__ beta, float* __restrict__ aff,
                      int C, float invN) {
    int c = threadIdx.x;
    if (c < C) {
        float mean = (float)(stats[c] * (double)invN);
        float ex2 = (float)(stats[C + c] * (double)invN);
        float var = ex2 - mean * mean;
        float a = gamma[c] * rsqrtf(var + 1e-5f);
        aff[c] = a;
        aff[C + c] = beta[c] - mean * a;
    }
}

// ---------------- tower stage 2: out = relu(in*a+c) @ W + b ----------------
__global__ __launch_bounds__(256) void k_tower2(
    const float* __restrict__ in, const float* __restrict__ aff,
    const float* __restrict__ W, const float* __restrict__ b,
    float* __restrict__ out, int N) {
    __shared__ __align__(16) float As_[64 * AS];
    __shared__ __align__(16) float Ws_[64 * WS];
    int t = threadIdx.x, tx = t & 15, ty = t >> 4;
    int rowBase = blockIdx.x * 64;

    loadA_bnrelu(in, aff, rowBase, N, As_);
    loadW(W, Ws_);
    __syncthreads();
    float acc[4][4] = {};
    mma64(As_, Ws_, ty, tx, acc);

    float4 bias = *(const float4*)(b + tx * 4);
#pragma unroll
    for (int i = 0; i < 4; i++) {
        int row = rowBase + ty * 4 + i;
        if (row < N) {
            *(float4*)(out + (size_t)row * 64 + tx * 4) =
                make_float4(acc[i][0] + bias.x, acc[i][1] + bias.y,
                            acc[i][2] + bias.z, acc[i][3] + bias.w);
        }
    }
}

// ---------------- edge pass 1: y1 = (x_u[src]*x_v[dst]) @ Wuv1 + buv1, stats ----------------
__global__ __launch_bounds__(256) void k_edge1(
    const float* __restrict__ xu, const float* __restrict__ xv,
    const int* __restrict__ es, const int* __restrict__ ed,
    const float* __restrict__ W, const float* __restrict__ b,
    float* __restrict__ out, double* __restrict__ stats) {
    __shared__ __align__(16) float As_[64 * AS];
    __shared__ __align__(16) float Ws_[64 * WS];
    __shared__ float ssum[64], ssq[64];
    int t = threadIdx.x, tx = t & 15, ty = t >> 4;
    if (t < 64) { ssum[t] = 0.f; ssq[t] = 0.f; }
    int rowBase = blockIdx.x * 64;

    {   // gather + elementwise product into A tile (ER % 64 == 0, no guard needed)
        int r = t >> 2, cg = (t & 3) << 4;
        int e = rowBase + r;
        int s = __ldg(es + e), d = __ldg(ed + e);
        const float4* pu = (const float4*)(xu + (size_t)s * 64 + cg);
        const float4* pv = (const float4*)(xv + (size_t)d * 64 + cg);
#pragma unroll
        for (int j = 0; j < 4; j++) {
            float4 a = __ldg(pu + j);
            float4 v = __ldg(pv + j);
            *(float4*)(As_ + r * AS + cg + 4 * j) =
                make_float4(a.x * v.x, a.y * v.y, a.z * v.z, a.w * v.w);
        }
    }
    loadW(W, Ws_);
    __syncthreads();
    float acc[4][4] = {};
    mma64(As_, Ws_, ty, tx, acc);

    float4 bias = *(const float4*)(b + tx * 4);
    float cs[4] = {0, 0, 0, 0}, cq[4] = {0, 0, 0, 0};
#pragma unroll
    for (int i = 0; i < 4; i++) {
        int row = rowBase + ty * 4 + i;
        float v0 = acc[i][0] + bias.x, v1 = acc[i][1] + bias.y;
        float v2 = acc[i][2] + bias.z, v3 = acc[i][3] + bias.w;
        *(float4*)(out + (size_t)row * 64 + tx * 4) = make_float4(v0, v1, v2, v3);
        cs[0] += v0; cq[0] += v0 * v0;
        cs[1] += v1; cq[1] += v1 * v1;
        cs[2] += v2; cq[2] += v2 * v2;
        cs[3] += v3; cq[3] += v3 * v3;
    }
#pragma unroll
    for (int j = 0; j < 4; j++) {
        atomicAdd(&ssum[tx * 4 + j], cs[j]);
        atomicAdd(&ssq[tx * 4 + j], cq[j]);
    }
    __syncthreads();
    if (t < 64) atomicAdd(&stats[t], (double)ssum[t]);
    else if (t < 128) atomicAdd(&stats[t], (double)ssq[t - 64]);
}

// ---------------- edge pass 2: y2 = relu(y1*a1+c1) @ Wuv2 + buv2 (64->16), stats ----------------
__global__ __launch_bounds__(256) void k_edge2(
    const float* __restrict__ y1, const float* __restrict__ aff,
    const float* __restrict__ W, const float* __restrict__ b,
    float* __restrict__ y2, double* __restrict__ stats) {
    __shared__ __align__(16) float As_[64 * AS];
    __shared__ __align__(16) float Ws2_[64 * 16];
    __shared__ float ssum[16], ssq[16];
    int t = threadIdx.x;
    if (t < 16) { ssum[t] = 0.f; ssq[t] = 0.f; }
    int rowBase = blockIdx.x * 64;

    loadA_bnrelu(y1, aff, rowBase, ERc, As_);
    {   // W is 64x16 = 1024 floats; 256 threads x 4
        int idx = t * 4;
        *(float4*)(Ws2_ + idx) = *(const float4*)(W + idx);
    }
    __syncthreads();

    int col = t & 15, ty = t >> 4;  // rows ty*4 .. ty*4+3
    float acc[4] = {0, 0, 0, 0};
#pragma unroll 8
    for (int k = 0; k < 64; k++) {
        float bw = Ws2_[k * 16 + col];
        acc[0] += As_[(ty * 4 + 0) * AS + k] * bw;
        acc[1] += As_[(ty * 4 + 1) * AS + k] * bw;
        acc[2] += As_[(ty * 4 + 2) * AS + k] * bw;
        acc[3] += As_[(ty * 4 + 3) * AS + k] * bw;
    }
    float bias = __ldg(b + col);
    float cs = 0.f, cq = 0.f;
#pragma unroll
    for (int i = 0; i < 4; i++) {
        float v = acc[i] + bias;
        y2[(size_t)(rowBase + ty * 4 + i) * 16 + col] = v;
        cs += v; cq += v * v;
    }
    atomicAdd(&ssum[col], cs);
    atomicAdd(&ssq[col], cq);
    __syncthreads();
    if (t < 16) atomicAdd(&stats[t], (double)ssum[t]);
    else if (t < 32) atomicAdd(&stats[t], (double)ssq[t - 16]);
}

// ---------------- edge pass 3: scores = relu(y2*a2+c2) . w3 + b3 ----------------
__global__ __launch_bounds__(256) void k_edge3(
    const float* __restrict__ y2, const float* __restrict__ aff,
    const float* __restrict__ w3, const float* __restrict__ b3,
    float* __restrict__ out) {
    int e = blockIdx.x * blockDim.x + threadIdx.x;
    if (e >= ERc) return;
    const float4* p = (const float4*)(y2 + (size_t)e * 16);
    float s = 0.f;
#pragma unroll
    for (int j = 0; j < 4; j++) {
        float4 v = __ldg(p + j);
        float4 a = *(const float4*)(aff + 4 * j);
        float4 c = *(const float4*)(aff + 16 + 4 * j);
        float4 w = *(const float4*)(w3 + 4 * j);
        s += fmaxf(v.x * a.x + c.x, 0.f) * w.x;
        s += fmaxf(v.y * a.y + c.y, 0.f) * w.y;
        s += fmaxf(v.z * a.z + c.z, 0.f) * w.z;
        s += fmaxf(v.w * a.w + c.w, 0.f) * w.w;
    }
    out[e] = s + __ldg(b3);
}

// ---------------- host ----------------
extern "C" void kernel_launch(void* const* d_in, const int* in_sizes, int n_in,
                              void* d_out, int out_size) {
    const float* u2e     = (const float*)d_in[0];
    const float* v2e     = (const float*)d_in[1];
    const float* W_self  = (const float*)d_in[2];
    const float* b_self  = (const float*)d_in[3];
    const float* W_neigh = (const float*)d_in[4];
    const float* Wur1 = (const float*)d_in[5];
    const float* bur1 = (const float*)d_in[6];
    const float* Wur2 = (const float*)d_in[7];
    const float* bur2 = (const float*)d_in[8];
    const float* Wvr1 = (const float*)d_in[9];
    const float* bvr1 = (const float*)d_in[10];
    const float* Wvr2 = (const float*)d_in[11];
    const float* bvr2 = (const float*)d_in[12];
    const float* Wuv1 = (const float*)d_in[13];
    const float* buv1 = (const float*)d_in[14];
    const float* Wuv2 = (const float*)d_in[15];
    const float* buv2 = (const float*)d_in[16];
    const float* Wuv3 = (const float*)d_in[17];
    const float* buv3 = (const float*)d_in[18];
    const float* bn_gamma  = (const float*)d_in[19];
    const float* bn_beta   = (const float*)d_in[20];
    const float* bn4_gamma = (const float*)d_in[21];
    const float* bn4_beta  = (const float*)d_in[22];
    const int* social_src = (const int*)d_in[23];
    const int* social_dst = (const int*)d_in[24];
    const int* rates_src  = (const int*)d_in[25];
    const int* rates_dst  = (const int*)d_in[26];
    float* out = (float*)d_out;

    // resolve scratch symbol addresses (pure lookups — legal during capture)
    void *p_ssoc, *p_sru, *p_srv, *p_degs, *p_degru, *p_degrv;
    void *p_hu, *p_hv, *p_tu, *p_tv, *p_xu, *p_xv, *p_y1, *p_y2;
    void *p_stU, *p_stV, *p_st1, *p_st2, *p_aU, *p_aV, *p_a1, *p_a2;
    cudaGetSymbolAddress(&p_ssoc, g_s_social);
    cudaGetSymbolAddress(&p_sru, g_s_ru);
    cudaGetSymbolAddress(&p_srv, g_s_rv);
    cudaGetSymbolAddress(&p_degs, g_deg_s);
    cudaGetSymbolAddress(&p_degru, g_deg_ru);
    cudaGetSymbolAddress(&p_degrv, g_deg_rv);
    cudaGetSymbolAddress(&p_hu, g_hu);
    cudaGetSymbolAddress(&p_hv, g_hv);
    cudaGetSymbolAddress(&p_tu, g_tu);
    cudaGetSymbolAddress(&p_tv, g_tv);
    cudaGetSymbolAddress(&p_xu, g_xu);
    cudaGetSymbolAddress(&p_xv, g_xv);
    cudaGetSymbolAddress(&p_y1, g_y1);
    cudaGetSymbolAddress(&p_y2, g_y2);
    cudaGetSymbolAddress(&p_stU, g_statU);
    cudaGetSymbolAddress(&p_stV, g_statV);
    cudaGetSymbolAddress(&p_st1, g_stat1);
    cudaGetSymbolAddress(&p_st2, g_stat2);
    cudaGetSymbolAddress(&p_aU, g_affU);
    cudaGetSymbolAddress(&p_aV, g_affV);
    cudaGetSymbolAddress(&p_a1, g_aff1);
    cudaGetSymbolAddress(&p_a2, g_aff2);

    const int NB_U = (NUc + 63) / 64;   // 782
    const int NB_V = (NVc + 63) / 64;   // 782
    const int NB_E = ERc / 64;          // 15625

    k_zero<<<2048, 256>>>();

    // segment sums: social (u->u), rated (v->u), rates (u->v)
    k_scatter<<<(ESc + 7) / 8, 256>>>(u2e, social_src, social_dst,
                                      (float*)p_ssoc, (float*)p_degs, ESc);
    k_scatter<<<(ERc + 7) / 8, 256>>>(v2e, rates_dst, rates_src,
                                      (float*)p_sru, (float*)p_degru, ERc);
    k_scatter<<<(ERc + 7) / 8, 256>>>(u2e, rates_src, rates_dst,
                                      (float*)p_srv, (float*)p_degrv, ERc);

    k_comb_user<<<NB_U, 256>>>(u2e, W_self, b_self, W_neigh, (float*)p_hu);
    k_comb_item<<<NB_V, 256>>>(v2e, W_self, b_self, W_neigh, (float*)p_hv);

    k_tower1<<<NB_U, 256>>>((const float*)p_hu, Wur1, bur1, (float*)p_tu, (double*)p_stU, NUc);
    k_tower1<<<NB_V, 256>>>((const float*)p_hv, Wvr1, bvr1, (float*)p_tv, (double*)p_stV, NVc);
    k_fin<<<1, 64>>>((const double*)p_stU, bn_gamma + 0, bn_beta + 0, (float*)p_aU, 64, 1.0f / NUc);
    k_fin<<<1, 64>>>((const double*)p_stV, bn_gamma + 64, bn_beta + 64, (float*)p_aV, 64, 1.0f / NVc);
    k_tower2<<<NB_U, 256>>>((const float*)p_tu, (const float*)p_aU, Wur2, bur2, (float*)p_xu, NUc);
    k_tower2<<<NB_V, 256>>>((const float*)p_tv, (const float*)p_aV, Wvr2, bvr2, (float*)p_xv, NVc);

    k_edge1<<<NB_E, 256>>>((const float*)p_xu, (const float*)p_xv, rates_src, rates_dst,
                           Wuv1, buv1, (float*)p_y1, (double*)p_st1);
    k_fin<<<1, 64>>>((const double*)p_st1, bn_gamma + 128, bn_beta + 128, (float*)p_a1, 64, 1.0f / ERc);
    k_edge2<<<NB_E, 256>>>((const float*)p_y1, (const float*)p_a1, Wuv2, buv2,
                           (float*)p_y2, (double*)p_st2);
    k_fin<<<1, 16>>>((const double*)p_st2, bn4_gamma, bn4_beta, (float*)p_a2, 16, 1.0f / ERc);
    k_edge3<<<(ERc + 255) / 256, 256>>>((const float*)p_y2, (const float*)p_a2, Wuv3, buv3, out);

    (void)in_sizes; (void)n_in; (void)out_size;
}

// round 7
// speedup vs baseline: 1.1460x; 1.1460x over previous
#include <cuda_runtime.h>
#include <cuda_bf16.h>
#include <cstdint>

#define NUc 50000
#define NVc 50000
#define ESc 800000
#define ERc 1000000
#define AS 68   // smem A-tile stride (floats) for FFMA GEMMs
#define WS 68

// ---------------- device scratch (no allocations allowed) ----------------
__device__ __align__(16) float g_s_social[(size_t)NUc * 64];
__device__ __align__(16) float g_s_ru[(size_t)NUc * 64];
__device__ __align__(16) float g_s_rv[(size_t)NVc * 64];
__device__ float g_deg_s[NUc];
__device__ float g_deg_ru[NUc];
__device__ float g_deg_rv[NVc];
__device__ __align__(16) float g_hu[(size_t)NUc * 64];
__device__ __align__(16) float g_hv[(size_t)NVc * 64];
__device__ __align__(16) float g_tu[(size_t)NUc * 64];
__device__ __align__(16) float g_tv[(size_t)NVc * 64];
__device__ __align__(16) float g_xu[(size_t)NUc * 64];
__device__ __align__(16) float g_xv[(size_t)NVc * 64];
__device__ __align__(16) float g_y1[(size_t)ERc * 64];   // 256 MB
__device__ __align__(16) float g_y2[(size_t)ERc * 16];   // 64 MB
__device__ double g_statU[128];
__device__ double g_statV[128];
__device__ double g_stat1[128];
__device__ double g_stat2[32];
__device__ __align__(16) float g_affU[128];
__device__ __align__(16) float g_affV[128];
__device__ __align__(16) float g_aff1[128];
__device__ __align__(16) float g_aff2[32];
// Wuv1 pre-packed into per-lane m16n8k16 B-fragment order (hi/lo bf16 split)
__device__ __align__(16) uint32_t g_fragH[2048];
__device__ __align__(16) uint32_t g_fragL[2048];

// ---------------- zero scratch ----------------
__global__ void k_zero() {
    size_t tid = (size_t)blockIdx.x * blockDim.x + threadIdx.x;
    size_t stride = (size_t)gridDim.x * blockDim.x;
    const size_t n4 = (size_t)NUc * 16;
    float4 z = make_float4(0.f, 0.f, 0.f, 0.f);
    for (size_t j = tid; j < n4; j += stride) {
        ((float4*)g_s_social)[j] = z;
        ((float4*)g_s_ru)[j] = z;
        ((float4*)g_s_rv)[j] = z;
    }
    for (size_t j = tid; j < NUc; j += stride) {
        g_deg_s[j] = 0.f;
        g_deg_ru[j] = 0.f;
        g_deg_rv[j] = 0.f;
    }
    if (tid < 128) { g_statU[tid] = 0.0; g_statV[tid] = 0.0; g_stat1[tid] = 0.0; }
    if (tid < 32) g_stat2[tid] = 0.0;
}

// ---------------- prep: pack Wuv1 into mma B-fragment layout, bf16 hi/lo ----------------
// frag index = (kt*8+nt)*64 + lane*2 + r  (kt in 0..3, nt in 0..7, r = b0/b1)
// b0 (r=0): k = kt*16 + 2*tig + {0,1};  b1 (r=1): k = kt*16 + 2*tig + 8 + {0,1}
// n = nt*8 + (lane>>2);  W is [k][n] row-major (64x64)
__global__ void k_prepW(const float* __restrict__ W) {
    int t = threadIdx.x;
    for (int idx = t; idx < 2048; idx += 256) {
        int r = idx & 1;
        int lane = (idx >> 1) & 31;
        int grp = idx >> 6;
        int kt = grp >> 3, nt = grp & 7;
        int g = lane >> 2, tig = lane & 3;
        int n = nt * 8 + g;
        int k0 = kt * 16 + 2 * tig + (r ? 8 : 0);
        float w0 = __ldg(W + k0 * 64 + n);
        float w1 = __ldg(W + (k0 + 1) * 64 + n);
        __nv_bfloat16 h0 = __float2bfloat16(w0), h1 = __float2bfloat16(w1);
        float l0 = w0 - __bfloat162float(h0);
        float l1 = w1 - __bfloat162float(h1);
        __nv_bfloat162 hh; hh.x = h0; hh.y = h1;
        __nv_bfloat162 ll; ll.x = __float2bfloat16(l0); ll.y = __float2bfloat16(l1);
        g_fragH[idx] = *(const uint32_t*)&hh;
        g_fragL[idx] = *(const uint32_t*)&ll;
    }
}

// ---------------- edge scatter: acc[dst] += feat[src] via red.v4 ----------------
__global__ __launch_bounds__(256) void k_scatter(
    const float* __restrict__ feat, const int* __restrict__ src,
    const int* __restrict__ dst, float* __restrict__ acc,
    float* __restrict__ deg, int E) {
    int g = blockIdx.x * blockDim.x + threadIdx.x;
    int e = g >> 4;
    int q = g & 15;
    if (e >= E) return;
    int s = __ldg(src + e);
    int d = __ldg(dst + e);
    float4 v = __ldg((const float4*)feat + (size_t)s * 16 + q);
    float* p = acc + (size_t)d * 64 + q * 4;
    asm volatile("red.global.add.v4.f32 [%0], {%1, %2, %3, %4};"
                 :: "l"(p), "f"(v.x), "f"(v.y), "f"(v.z), "f"(v.w) : "memory");
    if (q == 0) atomicAdd(deg + d, 1.0f);
}

// ---------------- shared GEMM helpers (64-row block, 256 threads) ----------------
__device__ __forceinline__ void mma64(const float* __restrict__ As_,
                                      const float* __restrict__ Ws_,
                                      int ty, int tx, float acc[4][4]) {
#pragma unroll 16
    for (int k = 0; k < 64; k++) {
        float4 b = *(const float4*)(Ws_ + k * WS + tx * 4);
        float a0 = As_[(ty * 4 + 0) * AS + k];
        float a1 = As_[(ty * 4 + 1) * AS + k];
        float a2 = As_[(ty * 4 + 2) * AS + k];
        float a3 = As_[(ty * 4 + 3) * AS + k];
        acc[0][0] += a0 * b.x; acc[0][1] += a0 * b.y; acc[0][2] += a0 * b.z; acc[0][3] += a0 * b.w;
        acc[1][0] += a1 * b.x; acc[1][1] += a1 * b.y; acc[1][2] += a1 * b.z; acc[1][3] += a1 * b.w;
        acc[2][0] += a2 * b.x; acc[2][1] += a2 * b.y; acc[2][2] += a2 * b.z; acc[2][3] += a2 * b.w;
        acc[3][0] += a3 * b.x; acc[3][1] += a3 * b.y; acc[3][2] += a3 * b.z; acc[3][3] += a3 * b.w;
    }
}

__device__ __forceinline__ void loadW(const float* __restrict__ W, float* __restrict__ Ws_) {
    int t = threadIdx.x, r = t >> 2, cg = (t & 3) << 4;
#pragma unroll
    for (int j = 0; j < 16; j += 4) {
        float4 v = *(const float4*)(W + r * 64 + cg + j);
        *(float4*)(Ws_ + r * WS + cg + j) = v;
    }
}

__device__ __forceinline__ void loadWsum(const float* __restrict__ Wa, const float* __restrict__ Wb,
                                         float* __restrict__ Ws_) {
    int t = threadIdx.x, r = t >> 2, cg = (t & 3) << 4;
#pragma unroll
    for (int j = 0; j < 16; j += 4) {
        float4 a = *(const float4*)(Wa + r * 64 + cg + j);
        float4 b = *(const float4*)(Wb + r * 64 + cg + j);
        *(float4*)(Ws_ + r * WS + cg + j) = make_float4(a.x + b.x, a.y + b.y, a.z + b.z, a.w + b.w);
    }
}

__device__ __forceinline__ void loadA_plain(const float* __restrict__ src, int rowBase, int N,
                                            float* __restrict__ As_) {
    int t = threadIdx.x, r = t >> 2, cg = (t & 3) << 4;
    int row = rowBase + r;
#pragma unroll
    for (int j = 0; j < 16; j += 4) {
        float4 v = make_float4(0.f, 0.f, 0.f, 0.f);
        if (row < N) v = *(const float4*)(src + (size_t)row * 64 + cg + j);
        *(float4*)(As_ + r * AS + cg + j) = v;
    }
}

__device__ __forceinline__ void loadA_mean(const float* __restrict__ src, const float* __restrict__ deg,
                                           int rowBase, int N, float* __restrict__ As_) {
    int t = threadIdx.x, r = t >> 2, cg = (t & 3) << 4;
    int row = rowBase + r;
    float sc = 0.f;
    if (row < N) sc = 1.f / fmaxf(__ldg(deg + row), 1.f);
#pragma unroll
    for (int j = 0; j < 16; j += 4) {
        float4 v = make_float4(0.f, 0.f, 0.f, 0.f);
        if (row < N) {
            v = *(const float4*)(src + (size_t)row * 64 + cg + j);
            v.x *= sc; v.y *= sc; v.z *= sc; v.w *= sc;
        }
        *(float4*)(As_ + r * AS + cg + j) = v;
    }
}

__device__ __forceinline__ void loadA_bnrelu(const float* __restrict__ src, const float* __restrict__ aff,
                                             int rowBase, int N, float* __restrict__ As_) {
    int t = threadIdx.x, r = t >> 2, cg = (t & 3) << 4;
    int row = rowBase + r;
#pragma unroll
    for (int j = 0; j < 16; j += 4) {
        float4 v = make_float4(0.f, 0.f, 0.f, 0.f);
        if (row < N) {
            v = *(const float4*)(src + (size_t)row * 64 + cg + j);
            float4 a = *(const float4*)(aff + cg + j);
            float4 c = *(const float4*)(aff + 64 + cg + j);
            v.x = fmaxf(v.x * a.x + c.x, 0.f);
            v.y = fmaxf(v.y * a.y + c.y, 0.f);
            v.z = fmaxf(v.z * a.z + c.z, 0.f);
            v.w = fmaxf(v.w * a.w + c.w, 0.f);
        }
        *(float4*)(As_ + r * AS + cg + j) = v;
    }
}

// ---------------- node combine: user ----------------
__global__ __launch_bounds__(256) void k_comb_user(
    const float* __restrict__ u2e, const float* __restrict__ Wself,
    const float* __restrict__ bself, const float* __restrict__ Wneigh,
    float* __restrict__ out) {
    __shared__ __align__(16) float As_[64 * AS];
    __shared__ __align__(16) float Ws_[64 * WS];
    int t = threadIdx.x, tx = t & 15, ty = t >> 4;
    int rowBase = blockIdx.x * 64;
    float acc[4][4] = {};

    loadA_plain(u2e, rowBase, NUc, As_);
    loadWsum(Wself, Wself + 2 * 4096, Ws_);
    __syncthreads();
    mma64(As_, Ws_, ty, tx, acc);
    __syncthreads();

    loadA_mean(g_s_social, g_deg_s, rowBase, NUc, As_);
    loadW(Wneigh, Ws_);
    __syncthreads();
    mma64(As_, Ws_, ty, tx, acc);
    __syncthreads();

    loadA_mean(g_s_ru, g_deg_ru, rowBase, NUc, As_);
    loadW(Wneigh + 2 * 4096, Ws_);
    __syncthreads();
    mma64(As_, Ws_, ty, tx, acc);

    float4 b0 = *(const float4*)(bself + tx * 4);
    float4 b2 = *(const float4*)(bself + 128 + tx * 4);
    float4 bias = make_float4(b0.x + b2.x, b0.y + b2.y, b0.z + b2.z, b0.w + b2.w);
#pragma unroll
    for (int i = 0; i < 4; i++) {
        int row = rowBase + ty * 4 + i;
        if (row < NUc) {
            *(float4*)(out + (size_t)row * 64 + tx * 4) =
                make_float4(acc[i][0] + bias.x, acc[i][1] + bias.y,
                            acc[i][2] + bias.z, acc[i][3] + bias.w);
        }
    }
}

// ---------------- node combine: item ----------------
__global__ __launch_bounds__(256) void k_comb_item(
    const float* __restrict__ v2e, const float* __restrict__ Wself,
    const float* __restrict__ bself, const float* __restrict__ Wneigh,
    float* __restrict__ out) {
    __shared__ __align__(16) float As_[64 * AS];
    __shared__ __align__(16) float Ws_[64 * WS];
    int t = threadIdx.x, tx = t & 15, ty = t >> 4;
    int rowBase = blockIdx.x * 64;
    float acc[4][4] = {};

    loadA_plain(v2e, rowBase, NVc, As_);
    loadW(Wself + 4096, Ws_);
    __syncthreads();
    mma64(As_, Ws_, ty, tx, acc);
    __syncthreads();

    loadA_mean(g_s_rv, g_deg_rv, rowBase, NVc, As_);
    loadW(Wneigh + 4096, Ws_);
    __syncthreads();
    mma64(As_, Ws_, ty, tx, acc);

    float4 bias = *(const float4*)(bself + 64 + tx * 4);
#pragma unroll
    for (int i = 0; i < 4; i++) {
        int row = rowBase + ty * 4 + i;
        if (row < NVc) {
            *(float4*)(out + (size_t)row * 64 + tx * 4) =
                make_float4(acc[i][0] + bias.x, acc[i][1] + bias.y,
                            acc[i][2] + bias.z, acc[i][3] + bias.w);
        }
    }
}

// ---------------- tower stage 1: out = in@W + b, column stats ----------------
__global__ __launch_bounds__(256) void k_tower1(
    const float* __restrict__ in, const float* __restrict__ W, const float* __restrict__ b,
    float* __restrict__ out, double* __restrict__ stats, int N) {
    __shared__ __align__(16) float As_[64 * AS];
    __shared__ __align__(16) float Ws_[64 * WS];
    __shared__ float ssum[64], ssq[64];
    int t = threadIdx.x, tx = t & 15, ty = t >> 4;
    if (t < 64) { ssum[t] = 0.f; ssq[t] = 0.f; }
    int rowBase = blockIdx.x * 64;

    loadA_plain(in, rowBase, N, As_);
    loadW(W, Ws_);
    __syncthreads();
    float acc[4][4] = {};
    mma64(As_, Ws_, ty, tx, acc);

    float4 bias = *(const float4*)(b + tx * 4);
    float cs[4] = {0, 0, 0, 0}, cq[4] = {0, 0, 0, 0};
#pragma unroll
    for (int i = 0; i < 4; i++) {
        int row = rowBase + ty * 4 + i;
        if (row < N) {
            float v0 = acc[i][0] + bias.x, v1 = acc[i][1] + bias.y;
            float v2 = acc[i][2] + bias.z, v3 = acc[i][3] + bias.w;
            *(float4*)(out + (size_t)row * 64 + tx * 4) = make_float4(v0, v1, v2, v3);
            cs[0] += v0; cq[0] += v0 * v0;
            cs[1] += v1; cq[1] += v1 * v1;
            cs[2] += v2; cq[2] += v2 * v2;
            cs[3] += v3; cq[3] += v3 * v3;
        }
    }
#pragma unroll
    for (int j = 0; j < 4; j++) {
        atomicAdd(&ssum[tx * 4 + j], cs[j]);
        atomicAdd(&ssq[tx * 4 + j], cq[j]);
    }
    __syncthreads();
    if (t < 64) atomicAdd(&stats[t], (double)ssum[t]);
    else if (t < 128) atomicAdd(&stats[t], (double)ssq[t - 64]);
}

// ---------------- BN finalize ----------------
__global__ void k_fin(const double* __restrict__ stats, const float* __restrict__ gamma,
                      const float* __restrict__ beta, float* __restrict__ aff,
                      int C, float invN) {
    int c = threadIdx.x;
    if (c < C) {
        float mean = (float)(stats[c] * (double)invN);
        float ex2 = (float)(stats[C + c] * (double)invN);
        float var = ex2 - mean * mean;
        float a = gamma[c] * rsqrtf(var + 1e-5f);
        aff[c] = a;
        aff[C + c] = beta[c] - mean * a;
    }
}

// ---------------- tower stage 2: out = relu(in*a+c) @ W + b ----------------
__global__ __launch_bounds__(256) void k_tower2(
    const float* __restrict__ in, const float* __restrict__ aff,
    const float* __restrict__ W, const float* __restrict__ b,
    float* __restrict__ out, int N) {
    __shared__ __align__(16) float As_[64 * AS];
    __shared__ __align__(16) float Ws_[64 * WS];
    int t = threadIdx.x, tx = t & 15, ty = t >> 4;
    int rowBase = blockIdx.x * 64;

    loadA_bnrelu(in, aff, rowBase, N, As_);
    loadW(W, Ws_);
    __syncthreads();
    float acc[4][4] = {};
    mma64(As_, Ws_, ty, tx, acc);

    float4 bias = *(const float4*)(b + tx * 4);
#pragma unroll
    for (int i = 0; i < 4; i++) {
        int row = rowBase + ty * 4 + i;
        if (row < N) {
            *(float4*)(out + (size_t)row * 64 + tx * 4) =
                make_float4(acc[i][0] + bias.x, acc[i][1] + bias.y,
                            acc[i][2] + bias.z, acc[i][3] + bias.w);
        }
    }
}

// ================= mma.sync edge pass 1 =================
// y1[e][:] = (x_u[src[e]] * x_v[dst[e]]) @ Wuv1 + buv1 via bf16 hi/lo split HMMA
// 128 edges/block, 8 warps, each warp: m16 x n64 x k64
#define E1_SMEM 51200
#define OFF_AH 0
#define OFF_AL 17408
#define OFF_BH 34816
#define OFF_BL 43008
#define AROW 136   // bytes per A row (64 bf16 = 128B + 8B pad)

__device__ __forceinline__ void mma16816(float c[4], uint32_t a0, uint32_t a1,
                                         uint32_t a2, uint32_t a3,
                                         uint32_t b0, uint32_t b1) {
    asm volatile(
        "mma.sync.aligned.m16n8k16.row.col.f32.bf16.bf16.f32 "
        "{%0,%1,%2,%3}, {%4,%5,%6,%7}, {%8,%9}, {%0,%1,%2,%3};"
        : "+f"(c[0]), "+f"(c[1]), "+f"(c[2]), "+f"(c[3])
        : "r"(a0), "r"(a1), "r"(a2), "r"(a3), "r"(b0), "r"(b1));
}

__global__ __launch_bounds__(256)
void k_edge1_mma(const float* __restrict__ xu, const float* __restrict__ xv,
                 const int* __restrict__ es, const int* __restrict__ ed,
                 const float* __restrict__ b, float* __restrict__ out,
                 double* __restrict__ stats) {
    extern __shared__ __align__(16) char smem[];
    __shared__ float ssum[64], ssq[64];
    int t = threadIdx.x, lane = t & 31, w = t >> 5;
    int rowBase = blockIdx.x * 128;
    if (t < 64) { ssum[t] = 0.f; ssq[t] = 0.f; }

    // ---- B fragments (hi/lo): 2048 u32 each, coalesced copy ----
    {
        const uint4* sH = (const uint4*)g_fragH;
        const uint4* sL = (const uint4*)g_fragL;
        uint4* dH = (uint4*)(smem + OFF_BH);
        uint4* dL = (uint4*)(smem + OFF_BL);
        dH[t] = __ldg(sH + t);
        dH[t + 256] = __ldg(sH + t + 256);
        dL[t] = __ldg(sL + t);
        dL[t + 256] = __ldg(sL + t + 256);
    }
    // ---- A: gather x_u*x_v, bf16 hi/lo split; row-major [128][64] bf16, 136B stride ----
    {
        int r = t >> 1, h = t & 1;  // 2 threads per edge row, 32 cols each
        int e = rowBase + r;
        char* aH = smem + OFF_AH + r * AROW + h * 64;
        char* aL = smem + OFF_AL + r * AROW + h * 64;
        if (e < ERc) {
            int s = __ldg(es + e), d = __ldg(ed + e);
            const float4* pu = (const float4*)(xu + (size_t)s * 64) + h * 8;
            const float4* pv = (const float4*)(xv + (size_t)d * 64) + h * 8;
#pragma unroll
            for (int j = 0; j < 8; j++) {
                float4 a = __ldg(pu + j), v = __ldg(pv + j);
                float x0 = a.x * v.x, x1 = a.y * v.y, x2 = a.z * v.z, x3 = a.w * v.w;
                __nv_bfloat162 h01 = __floats2bfloat162_rn(x0, x1);
                __nv_bfloat162 h23 = __floats2bfloat162_rn(x2, x3);
                float r0 = x0 - __bfloat162float(h01.x), r1 = x1 - __bfloat162float(h01.y);
                float r2 = x2 - __bfloat162float(h23.x), r3 = x3 - __bfloat162float(h23.y);
                __nv_bfloat162 l01 = __floats2bfloat162_rn(r0, r1);
                __nv_bfloat162 l23 = __floats2bfloat162_rn(r2, r3);
                *(uint2*)(aH + j * 8) = make_uint2(*(const uint32_t*)&h01, *(const uint32_t*)&h23);
                *(uint2*)(aL + j * 8) = make_uint2(*(const uint32_t*)&l01, *(const uint32_t*)&l23);
            }
        } else {
#pragma unroll
            for (int j = 0; j < 8; j++) {
                *(uint2*)(aH + j * 8) = make_uint2(0u, 0u);
                *(uint2*)(aL + j * 8) = make_uint2(0u, 0u);
            }
        }
    }
    __syncthreads();

    // ---- mma mainloop: D = AhiBhi + AhiBlo + AloBhi ----
    int g = lane >> 2, tig = lane & 3;
    int r0 = w * 16 + g;
    float acc[8][4] = {};
    const char* AH = smem + OFF_AH;
    const char* AL = smem + OFF_AL;
#pragma unroll
    for (int kt = 0; kt < 4; kt++) {
        int ka = kt * 32 + tig * 4;   // byte offset of k = kt*16 + 2*tig
        uint32_t aH0 = *(const uint32_t*)(AH + r0 * AROW + ka);
        uint32_t aH1 = *(const uint32_t*)(AH + (r0 + 8) * AROW + ka);
        uint32_t aH2 = *(const uint32_t*)(AH + r0 * AROW + ka + 16);
        uint32_t aH3 = *(const uint32_t*)(AH + (r0 + 8) * AROW + ka + 16);
        uint32_t aL0 = *(const uint32_t*)(AL + r0 * AROW + ka);
        uint32_t aL1 = *(const uint32_t*)(AL + (r0 + 8) * AROW + ka);
        uint32_t aL2 = *(const uint32_t*)(AL + r0 * AROW + ka + 16);
        uint32_t aL3 = *(const uint32_t*)(AL + (r0 + 8) * AROW + ka + 16);
#pragma unroll
        for (int nt = 0; nt < 8; nt++) {
            uint32_t boff = ((kt * 8 + nt) * 64 + lane * 2) * 4;
            uint2 bH = *(const uint2*)(smem + OFF_BH + boff);
            uint2 bL = *(const uint2*)(smem + OFF_BL + boff);
            mma16816(acc[nt], aH0, aH1, aH2, aH3, bH.x, bH.y);
            mma16816(acc[nt], aH0, aH1, aH2, aH3, bL.x, bL.y);
            mma16816(acc[nt], aL0, aL1, aL2, aL3, bH.x, bH.y);
        }
    }
    __syncthreads();   // A region is about to be overwritten by the stage

    // ---- stage C to smem (stride-65 f32) ----
    float* stage = (float*)smem;   // 128*65*4 = 33280 B, overlaps dead A tiles
#pragma unroll
    for (int nt = 0; nt < 8; nt++) {
        int c = nt * 8 + tig * 2;
        stage[r0 * 65 + c] = acc[nt][0];
        stage[r0 * 65 + c + 1] = acc[nt][1];
        stage[(r0 + 8) * 65 + c] = acc[nt][2];
        stage[(r0 + 8) * 65 + c + 1] = acc[nt][3];
    }
    __syncthreads();

    // ---- coalesced store + bias + stats (thread owns fixed 4 columns) ----
    int c4 = (t & 15) * 4;
    float4 bias = *(const float4*)(b + c4);
    float cs[4] = {0, 0, 0, 0}, cq[4] = {0, 0, 0, 0};
#pragma unroll
    for (int i = 0; i < 8; i++) {
        int r = (t >> 4) + 16 * i;
        int e = rowBase + r;
        if (e < ERc) {
            const float* sp = stage + r * 65 + c4;
            float v0 = sp[0] + bias.x, v1 = sp[1] + bias.y;
            float v2 = sp[2] + bias.z, v3 = sp[3] + bias.w;
            *(float4*)(out + (size_t)e * 64 + c4) = make_float4(v0, v1, v2, v3);
            cs[0] += v0; cq[0] += v0 * v0;
            cs[1] += v1; cq[1] += v1 * v1;
            cs[2] += v2; cq[2] += v2 * v2;
            cs[3] += v3; cq[3] += v3 * v3;
        }
    }
#pragma unroll
    for (int j = 0; j < 4; j++) {
        atomicAdd(&ssum[c4 + j], cs[j]);
        atomicAdd(&ssq[c4 + j], cq[j]);
    }
    __syncthreads();
    if (t < 64) atomicAdd(&stats[t], (double)ssum[t]);
    else if (t < 128) atomicAdd(&stats[t], (double)ssq[t - 64]);
}

// ---------------- edge pass 2: y2 = relu(y1*a1+c1) @ Wuv2 + buv2 (64->16), stats ----------------
__global__ __launch_bounds__(256) void k_edge2(
    const float* __restrict__ y1, const float* __restrict__ aff,
    const float* __restrict__ W, const float* __restrict__ b,
    float* __restrict__ y2, double* __restrict__ stats) {
    __shared__ __align__(16) float As_[64 * AS];
    __shared__ __align__(16) float Ws2_[64 * 16];
    __shared__ float ssum[16], ssq[16];
    int t = threadIdx.x;
    if (t < 16) { ssum[t] = 0.f; ssq[t] = 0.f; }
    int rowBase = blockIdx.x * 64;

    loadA_bnrelu(y1, aff, rowBase, ERc, As_);
    {
        int idx = t * 4;
        *(float4*)(Ws2_ + idx) = *(const float4*)(W + idx);
    }
    __syncthreads();

    int col = t & 15, ty = t >> 4;
    float acc[4] = {0, 0, 0, 0};
#pragma unroll 8
    for (int k = 0; k < 64; k++) {
        float bw = Ws2_[k * 16 + col];
        acc[0] += As_[(ty * 4 + 0) * AS + k] * bw;
        acc[1] += As_[(ty * 4 + 1) * AS + k] * bw;
        acc[2] += As_[(ty * 4 + 2) * AS + k] * bw;
        acc[3] += As_[(ty * 4 + 3) * AS + k] * bw;
    }
    float bias = __ldg(b + col);
    float cs = 0.f, cq = 0.f;
#pragma unroll
    for (int i = 0; i < 4; i++) {
        float v = acc[i] + bias;
        y2[(size_t)(rowBase + ty * 4 + i) * 16 + col] = v;
        cs += v; cq += v * v;
    }
    atomicAdd(&ssum[col], cs);
    atomicAdd(&ssq[col], cq);
    __syncthreads();
    if (t < 16) atomicAdd(&stats[t], (double)ssum[t]);
    else if (t < 32) atomicAdd(&stats[t], (double)ssq[t - 16]);
}

// ---------------- edge pass 3: scores = relu(y2*a2+c2) . w3 + b3 ----------------
__global__ __launch_bounds__(256) void k_edge3(
    const float* __restrict__ y2, const float* __restrict__ aff,
    const float* __restrict__ w3, const float* __restrict__ b3,
    float* __restrict__ out) {
    int e = blockIdx.x * blockDim.x + threadIdx.x;
    if (e >= ERc) return;
    const float4* p = (const float4*)(y2 + (size_t)e * 16);
    float s = 0.f;
#pragma unroll
    for (int j = 0; j < 4; j++) {
        float4 v = __ldg(p + j);
        float4 a = *(const float4*)(aff + 4 * j);
        float4 c = *(const float4*)(aff + 16 + 4 * j);
        float4 w = *(const float4*)(w3 + 4 * j);
        s += fmaxf(v.x * a.x + c.x, 0.f) * w.x;
        s += fmaxf(v.y * a.y + c.y, 0.f) * w.y;
        s += fmaxf(v.z * a.z + c.z, 0.f) * w.z;
        s += fmaxf(v.w * a.w + c.w, 0.f) * w.w;
    }
    out[e] = s + __ldg(b3);
}

// ---------------- host ----------------
extern "C" void kernel_launch(void* const* d_in, const int* in_sizes, int n_in,
                              void* d_out, int out_size) {
    const float* u2e     = (const float*)d_in[0];
    const float* v2e     = (const float*)d_in[1];
    const float* W_self  = (const float*)d_in[2];
    const float* b_self  = (const float*)d_in[3];
    const float* W_neigh = (const float*)d_in[4];
    const float* Wur1 = (const float*)d_in[5];
    const float* bur1 = (const float*)d_in[6];
    const float* Wur2 = (const float*)d_in[7];
    const float* bur2 = (const float*)d_in[8];
    const float* Wvr1 = (const float*)d_in[9];
    const float* bvr1 = (const float*)d_in[10];
    const float* Wvr2 = (const float*)d_in[11];
    const float* bvr2 = (const float*)d_in[12];
    const float* Wuv1 = (const float*)d_in[13];
    const float* buv1 = (const float*)d_in[14];
    const float* Wuv2 = (const float*)d_in[15];
    const float* buv2 = (const float*)d_in[16];
    const float* Wuv3 = (const float*)d_in[17];
    const float* buv3 = (const float*)d_in[18];
    const float* bn_gamma  = (const float*)d_in[19];
    const float* bn_beta   = (const float*)d_in[20];
    const float* bn4_gamma = (const float*)d_in[21];
    const float* bn4_beta  = (const float*)d_in[22];
    const int* social_src = (const int*)d_in[23];
    const int* social_dst = (const int*)d_in[24];
    const int* rates_src  = (const int*)d_in[25];
    const int* rates_dst  = (const int*)d_in[26];
    float* out = (float*)d_out;

    void *p_ssoc, *p_sru, *p_srv, *p_degs, *p_degru, *p_degrv;
    void *p_hu, *p_hv, *p_tu, *p_tv, *p_xu, *p_xv, *p_y1, *p_y2;
    void *p_stU, *p_stV, *p_st1, *p_st2, *p_aU, *p_aV, *p_a1, *p_a2;
    cudaGetSymbolAddress(&p_ssoc, g_s_social);
    cudaGetSymbolAddress(&p_sru, g_s_ru);
    cudaGetSymbolAddress(&p_srv, g_s_rv);
    cudaGetSymbolAddress(&p_degs, g_deg_s);
    cudaGetSymbolAddress(&p_degru, g_deg_ru);
    cudaGetSymbolAddress(&p_degrv, g_deg_rv);
    cudaGetSymbolAddress(&p_hu, g_hu);
    cudaGetSymbolAddress(&p_hv, g_hv);
    cudaGetSymbolAddress(&p_tu, g_tu);
    cudaGetSymbolAddress(&p_tv, g_tv);
    cudaGetSymbolAddress(&p_xu, g_xu);
    cudaGetSymbolAddress(&p_xv, g_xv);
    cudaGetSymbolAddress(&p_y1, g_y1);
    cudaGetSymbolAddress(&p_y2, g_y2);
    cudaGetSymbolAddress(&p_stU, g_statU);
    cudaGetSymbolAddress(&p_stV, g_statV);
    cudaGetSymbolAddress(&p_st1, g_stat1);
    cudaGetSymbolAddress(&p_st2, g_stat2);
    cudaGetSymbolAddress(&p_aU, g_affU);
    cudaGetSymbolAddress(&p_aV, g_affV);
    cudaGetSymbolAddress(&p_a1, g_aff1);
    cudaGetSymbolAddress(&p_a2, g_aff2);

    cudaFuncSetAttribute(k_edge1_mma, cudaFuncAttributeMaxDynamicSharedMemorySize, E1_SMEM);

    const int NB_U = (NUc + 63) / 64;
    const int NB_V = (NVc + 63) / 64;
    const int NB_E = ERc / 64;
    const int NB_E1 = (ERc + 127) / 128;

    k_zero<<<2048, 256>>>();
    k_prepW<<<1, 256>>>(Wuv1);

    // segment sums: social (u->u), rated (v->u), rates (u->v); 16 lanes per edge
    k_scatter<<<ESc / 16, 256>>>(u2e, social_src, social_dst,
                                 (float*)p_ssoc, (float*)p_degs, ESc);
    k_scatter<<<ERc / 16, 256>>>(v2e, rates_dst, rates_src,
                                 (float*)p_sru, (float*)p_degru, ERc);
    k_scatter<<<ERc / 16, 256>>>(u2e, rates_src, rates_dst,
                                 (float*)p_srv, (float*)p_degrv, ERc);

    k_comb_user<<<NB_U, 256>>>(u2e, W_self, b_self, W_neigh, (float*)p_hu);
    k_comb_item<<<NB_V, 256>>>(v2e, W_self, b_self, W_neigh, (float*)p_hv);

    k_tower1<<<NB_U, 256>>>((const float*)p_hu, Wur1, bur1, (float*)p_tu, (double*)p_stU, NUc);
    k_tower1<<<NB_V, 256>>>((const float*)p_hv, Wvr1, bvr1, (float*)p_tv, (double*)p_stV, NVc);
    k_fin<<<1, 64>>>((const double*)p_stU, bn_gamma + 0, bn_beta + 0, (float*)p_aU, 64, 1.0f / NUc);
    k_fin<<<1, 64>>>((const double*)p_stV, bn_gamma + 64, bn_beta + 64, (float*)p_aV, 64, 1.0f / NVc);
    k_tower2<<<NB_U, 256>>>((const float*)p_tu, (const float*)p_aU, Wur2, bur2, (float*)p_xu, NUc);
    k_tower2<<<NB_V, 256>>>((const float*)p_tv, (const float*)p_aV, Wvr2, bvr2, (float*)p_xv, NVc);

    k_edge1_mma<<<NB_E1, 256, E1_SMEM>>>((const float*)p_xu, (const float*)p_xv,
                                         rates_src, rates_dst, buv1,
                                         (float*)p_y1, (double*)p_st1);
    k_fin<<<1, 64>>>((const double*)p_st1, bn_gamma + 128, bn_beta + 128, (float*)p_a1, 64, 1.0f / ERc);
    k_edge2<<<NB_E, 256>>>((const float*)p_y1, (const float*)p_a1, Wuv2, buv2,
                           (float*)p_y2, (double*)p_st2);
    k_fin<<<1, 16>>>((const double*)p_st2, bn4_gamma, bn4_beta, (float*)p_a2, 16, 1.0f / ERc);
    k_edge3<<<(ERc + 255) / 256, 256>>>((const float*)p_y2, (const float*)p_a2, Wuv3, buv3, out);

    (void)in_sizes; (void)n_in; (void)out_size;
}